// round 13
// baseline (speedup 1.0000x reference)
#include <cuda_runtime.h>
#include <cuda_bf16.h>
#include <cuda_fp16.h>
#include <cstdint>

#define N_NODES  50000
#define SEQ      12
#define CH       128
#define BS       4
#define TM       64           // nodes per tile
#define NTHREADS 256
#define AP       136          // bf16 A-tile pitch (elements)
#define GP       132          // gate fp32 pitch
#define NCONV    96           // converter blocks (lowest IDs -> first wave)
#define ELEMS_PB (N_NODES*(CH/4))          // 1.6M uint2 per batch
#define CHUNK    ((ELEMS_PB + NCONV - 1)/NCONV)

typedef unsigned long long ull;
typedef unsigned int       uint32;

// ---- smem: A tile, overlaid by gate after MMA ----
#define SM_A0    0                      // A hi bf16 [64][AP]   17408 B
#define SM_A1    17408                  // A lo                 17408 B
#define SM_GATE  0                      // fp32 [64][GP] 33792 B, overlays A0+A1
#define SM_TOTAL 34816

// W fragments, coalesced: uint4 (h0,h1,l0,l1) at [((ns*8+kb)*4+nb)*32 + lane]
__device__ uint4 g_wfrag[4*8*4*32];     // 64 KB

// fp16 shadow of x: 4 halves per uint2 (51.2 MB, L2-resident)
__device__ uint2 g_xh[BS*N_NODES*(CH/4)];

// pipeline state (reset every launch)
__device__ int g_flag[BS];
__device__ int g_tilectr;

__device__ __forceinline__ ull fma2(ull a, ull b, ull c){ull d;asm("fma.rn.f32x2 %0,%1,%2,%3;":"=l"(d):"l"(a),"l"(b),"l"(c));return d;}
__device__ __forceinline__ ull mul2(ull a, ull b){ull d;asm("mul.rn.f32x2 %0,%1,%2;":"=l"(d):"l"(a),"l"(b));return d;}
__device__ __forceinline__ ull add2(ull a, ull b){ull d;asm("add.rn.f32x2 %0,%1,%2;":"=l"(d):"l"(a),"l"(b));return d;}
__device__ __forceinline__ ull dup2(float a){ull d;asm("mov.b64 %0,{%1,%1};":"=l"(d):"f"(a));return d;}
__device__ __forceinline__ ull pack2(float lo,float hi){ull d;asm("mov.b64 %0,{%1,%2};":"=l"(d):"f"(lo),"f"(hi));return d;}

__device__ __forceinline__ uint32 smem_u32(const void* p){
    uint32 a; asm("{.reg .u64 t; cvta.to.shared.u64 t,%1; cvt.u32.u64 %0,t;}":"=r"(a):"l"(p)); return a;
}
__device__ __forceinline__ int ld_acq(const int* p){
    int v; asm volatile("ld.acquire.gpu.global.b32 %0,[%1];":"=r"(v):"l"(p)); return v;
}
__device__ __forceinline__ void split2(float x, float y, uint32& hi, uint32& lo){
    __nv_bfloat16 bx = __float2bfloat16_rn(x), by = __float2bfloat16_rn(y);
    float rx = x - __bfloat162float(bx), ry = y - __bfloat162float(by);
    __nv_bfloat162 h; h.x = bx; h.y = by;
    __nv_bfloat162 l; l.x = __float2bfloat16_rn(rx); l.y = __float2bfloat16_rn(ry);
    hi = *reinterpret_cast<uint32*>(&h);
    lo = *reinterpret_cast<uint32*>(&l);
}
__device__ __forceinline__ void ldsm_x4(uint32& a0,uint32& a1,uint32& a2,uint32& a3, uint32 addr){
    asm volatile("ldmatrix.sync.aligned.m8n8.x4.shared.b16 {%0,%1,%2,%3},[%4];"
                 : "=r"(a0),"=r"(a1),"=r"(a2),"=r"(a3) : "r"(addr));
}
__device__ __forceinline__ void hmma2(float* c, const uint32* a, uint32 b0, uint32 b1){
    asm volatile("mma.sync.aligned.m16n8k16.row.col.f32.bf16.bf16.f32 "
                 "{%0,%1,%2,%3},{%4,%5,%6,%7},{%8,%9},{%0,%1,%2,%3};"
                 : "+f"(c[0]),"+f"(c[1]),"+f"(c[2]),"+f"(c[3])
                 : "r"(a[0]),"r"(a[1]),"r"(a[2]),"r"(a[3]),"r"(b0),"r"(b1));
}
__device__ __forceinline__ void ldg_cg_v4(const float* p, ull& x, ull& y){
    asm("ld.global.cg.v2.u64 {%0,%1},[%2];" : "=l"(x),"=l"(y) : "l"(p));
}
__device__ __forceinline__ void ldg_cg_v2u32(const uint2* p, uint32& a, uint32& b){
    asm("ld.global.cg.v2.u32 {%0,%1},[%2];" : "=r"(a),"=r"(b) : "l"(p));
}

// ---- reset kernel: zero flags + tile counter (runs before main every launch) ----
__global__ void reset_kernel()
{
    if (threadIdx.x < BS) g_flag[threadIdx.x] = 0;
    if (threadIdx.x == BS) g_tilectr = 0;
}

// ---- build kernel: HMMA B fragments, coalesced (h0,h1,l0,l1) ----
__global__ void build_wfrag_kernel(const float* __restrict__ gate_w)
{
    int slot = blockIdx.x*blockDim.x + threadIdx.x;   // 0..1023
    if (slot >= 4*8*32) return;
    int lane = slot & 31;
    int kb   = (slot >> 5) & 7;
    int ns   = slot >> 8;
    #pragma unroll
    for (int nb = 0; nb < 4; nb++) {
        int n = ns*32 + nb*8 + (lane >> 2);
        uint32 h[2], l[2];
        #pragma unroll
        for (int i = 0; i < 2; i++) {
            int k0 = kb*16 + i*8 + (lane & 3)*2;
            split2(gate_w[n*CH + k0], gate_w[n*CH + k0 + 1], h[i], l[i]);
        }
        uint4 v; v.x = h[0]; v.y = h[1]; v.z = l[0]; v.w = l[1];
        g_wfrag[(((ns << 3) + kb)*4 + nb)*32 + lane] = v;
    }
}

__global__ void __launch_bounds__(NTHREADS, 3)
gated_spiral_kernel(const float* __restrict__ x,
                    const int*   __restrict__ indices,
                    const float* __restrict__ weight,
                    const float* __restrict__ gate_b,
                    float*       __restrict__ out)
{
    extern __shared__ char smem[];
    __shared__ int s_t;
    const uint32 sb = smem_u32(smem);
    float* gate_s = (float*)(smem + SM_GATE);

    const int tid  = threadIdx.x;
    const int wid  = tid >> 5;
    const int lane = tid & 31;

    // ---- converter role: blocks 0..NCONV-1 convert x -> fp16 shadow, batch-major ----
    if (blockIdx.x < NCONV) {
        #pragma unroll 1
        for (int b = 0; b < BS; b++) {
            int base = b*ELEMS_PB + blockIdx.x*CHUNK;
            int end  = min(base + CHUNK, (b + 1)*ELEMS_PB);
            #pragma unroll 4
            for (int i = base + tid; i < end; i += NTHREADS) {
                float4 v;
                asm("ld.global.cs.v4.f32 {%0,%1,%2,%3},[%4];"
                    : "=f"(v.x),"=f"(v.y),"=f"(v.z),"=f"(v.w)
                    : "l"(reinterpret_cast<const float4*>(x) + i));
                __half2 h0 = __floats2half2_rn(v.x, v.y);
                __half2 h1 = __floats2half2_rn(v.z, v.w);
                uint2 o;
                o.x = *reinterpret_cast<uint32*>(&h0);
                o.y = *reinterpret_cast<uint32*>(&h1);
                g_xh[i] = o;
            }
            __threadfence();
            __syncthreads();
            if (tid == 0) atomicAdd(&g_flag[b], 1);
        }
    }

    const ull bias0 = *reinterpret_cast<const ull*>(gate_b + lane*4);
    const ull bias1 = *reinterpret_cast<const ull*>(gate_b + lane*4 + 2);

    // MMA role: 8 warps = 2m x 4n grid; warp tile m32 x n32
    const int ms = wid & 1;
    const int ns = wid >> 1;
    const uint32 aoff0 = (uint32)((ms*32      + (lane & 15))*AP + (lane >> 4)*8) * 2;
    const uint32 aoff1 = (uint32)((ms*32 + 16 + (lane & 15))*AP + (lane >> 4)*8) * 2;

    const int tiles_per_batch = (N_NODES + TM - 1) / TM;   // 782
    const int total_tiles     = BS * tiles_per_batch;      // 3128

    // ---- stage A tile (fp32 source: GEMM accuracy unchanged) ----
    auto stage = [&](int tt) {
        const int bb  = tt / tiles_per_batch;
        const int vv0 = (tt - bb * tiles_per_batch) * TM;
        const int nv  = min(TM, N_NODES - vv0);
        const float* xs = x + (size_t)bb * (size_t)N_NODES * CH;
        #pragma unroll
        for (int k = 0; k < 8; k++) {                  // 64*32 float4 / 256 thr
            int i  = tid + k*NTHREADS;
            int r  = i >> 5;
            int k4 = (i & 31) << 2;
            const float* p = xs + (size_t)(vv0 + min(r, nv - 1))*CH + k4;
            ull lo, hi2; ldg_cg_v4(p, lo, hi2);
            float2 v01 = *reinterpret_cast<float2*>(&lo);
            float2 v23 = *reinterpret_cast<float2*>(&hi2);
            uint32 h0,l0,h1,l1;
            split2(v01.x, v01.y, h0, l0);
            split2(v23.x, v23.y, h1, l1);
            uint32 o = (uint32)(r*AP + k4) * 2;
            *(ull*)(smem + SM_A0 + o) = ((ull)h1 << 32) | h0;
            *(ull*)(smem + SM_A1 + o) = ((ull)l1 << 32) | l0;
        }
    };

    // ---- dynamic tile grab (balances converter late-join) ----
    auto grab = [&]() {
        __syncthreads();                 // also: gather done before stage overwrites smem
        if (tid == 0) s_t = atomicAdd(&g_tilectr, 1);
        __syncthreads();
        return s_t;
    };

    int t = grab();
    if (t < total_tiles) stage(t);

    while (t < total_tiles) {
        const int b      = t / tiles_per_batch;
        const int v0     = (t - b * tiles_per_batch) * TM;
        const int nvalid = min(TM, N_NODES - v0);
        const uint2* __restrict__ xhb = g_xh + (size_t)b * (size_t)N_NODES * (CH/4);

        __syncthreads();   // A(t) visible

        // ---- HMMA: gate = A x W^T; one nb-fragment live at a time ----
        float acc[2][4][4];
        #pragma unroll
        for (int mi = 0; mi < 2; mi++)
            #pragma unroll
            for (int nb = 0; nb < 4; nb++)
                #pragma unroll
                for (int j = 0; j < 4; j++) acc[mi][nb][j] = 0.f;

        #pragma unroll
        for (int kb = 0; kb < 8; kb++) {
            const uint32 ko = kb*32;
            uint32 ah[2][4], al[2][4];
            ldsm_x4(ah[0][0],ah[0][1],ah[0][2],ah[0][3], sb + SM_A0 + aoff0 + ko);
            ldsm_x4(ah[1][0],ah[1][1],ah[1][2],ah[1][3], sb + SM_A0 + aoff1 + ko);
            ldsm_x4(al[0][0],al[0][1],al[0][2],al[0][3], sb + SM_A1 + aoff0 + ko);
            ldsm_x4(al[1][0],al[1][1],al[1][2],al[1][3], sb + SM_A1 + aoff1 + ko);
            const uint4* wp = g_wfrag + (((ns << 3) + kb) << 2)*32 + lane;
            #pragma unroll
            for (int nb = 0; nb < 4; nb++) {
                uint4 w = wp[nb*32];                    // (h0,h1,l0,l1)
                #pragma unroll
                for (int mi = 0; mi < 2; mi++) {
                    hmma2(acc[mi][nb], ah[mi], w.x, w.y);   // hi*hi
                    hmma2(acc[mi][nb], ah[mi], w.z, w.w);   // hi*lo
                    hmma2(acc[mi][nb], al[mi], w.x, w.y);   // lo*hi
                }
            }
        }
        __syncthreads();   // all ldsm retired before gate overlays A

        // ---- Epilogue: acc -> gate_s ----
        #pragma unroll
        for (int mi = 0; mi < 2; mi++) {
            int r0 = ms*32 + mi*16 + (lane >> 2);
            #pragma unroll
            for (int nb = 0; nb < 4; nb++) {
                int c = ns*32 + nb*8 + (lane & 3)*2;
                *reinterpret_cast<ull*>(gate_s + r0*GP + c)     = pack2(acc[mi][nb][0], acc[mi][nb][1]);
                *reinterpret_cast<ull*>(gate_s + (r0+8)*GP + c) = pack2(acc[mi][nb][2], acc[mi][nb][3]);
            }
        }

        // ---- wait for this batch's fp16 shadow (usually already set) ----
        if (tid == 0) {
            while (ld_acq(&g_flag[b]) < NCONV) { }
            __threadfence();
        }
        __syncthreads();   // gate visible + xh(b) ready

        // ---- Gather (fp16 source): warp-per-row; lane = 4 channels (8B LDG) ----
        #pragma unroll 1
        for (int nn = 0; nn < 8; nn++) {
            const int node = wid*8 + nn;
            if (node >= nvalid) break;
            const int base = (v0 + node)*SEQ;
            int4   ia = *reinterpret_cast<const int4*>(indices + base);
            int4   ib = *reinterpret_cast<const int4*>(indices + base + 4);
            int4   ic = *reinterpret_cast<const int4*>(indices + base + 8);
            float4 wa = *reinterpret_cast<const float4*>(weight + base);
            float4 wb = *reinterpret_cast<const float4*>(weight + base + 4);
            float4 wc = *reinterpret_cast<const float4*>(weight + base + 8);
            ull a0 = 0, a1 = 0;
            #define GACC(II, WW) { \
                const uint2* src = xhb + (size_t)(uint32)(II)*(CH/4) + lane; \
                uint32 u0, u1; ldg_cg_v2u32(src, u0, u1); \
                float2 f0 = __half22float2(*reinterpret_cast<__half2*>(&u0)); \
                float2 f1 = __half22float2(*reinterpret_cast<__half2*>(&u1)); \
                ull W = dup2(WW); \
                a0 = fma2(W, pack2(f0.x, f0.y), a0); \
                a1 = fma2(W, pack2(f1.x, f1.y), a1); }
            GACC(ia.x, wa.x) GACC(ia.y, wa.y) GACC(ia.z, wa.z) GACC(ia.w, wa.w)
            GACC(ib.x, wb.x) GACC(ib.y, wb.y) GACC(ib.z, wb.z) GACC(ib.w, wb.w)
            GACC(ic.x, wc.x) GACC(ic.y, wc.y) GACC(ic.z, wc.z) GACC(ic.w, wc.w)
            #undef GACC
            ulonglong2 gp = *reinterpret_cast<const ulonglong2*>(gate_s + node*GP + lane*4);
            ull o0 = mul2(a0, add2(gp.x, bias0));
            ull o1 = mul2(a1, add2(gp.y, bias1));
            float* op = out + ((size_t)b*N_NODES + (size_t)(v0 + node))*CH + lane*4;
            asm volatile("st.global.cs.v2.b64 [%0], {%1,%2};" :: "l"(op), "l"(o0), "l"(o1) : "memory");
        }

        // ---- next tile ----
        const int nxt = grab();          // grab() syncs: gather done before stage overwrites
        if (nxt < total_tiles) stage(nxt);
        t = nxt;
    }
}

extern "C" void kernel_launch(void* const* d_in, const int* in_sizes, int n_in,
                              void* d_out, int out_size)
{
    (void)in_sizes; (void)n_in; (void)out_size;
    const float* x       = (const float*)d_in[0];
    const int*   indices = (const int*)  d_in[1];
    const float* weight  = (const float*)d_in[2];
    const float* gate_w  = (const float*)d_in[3];
    const float* gate_b  = (const float*)d_in[4];
    float*       out     = (float*)d_out;

    reset_kernel<<<1, 32>>>();
    build_wfrag_kernel<<<4, 256>>>(gate_w);

    cudaFuncSetAttribute(gated_spiral_kernel,
                         cudaFuncAttributeMaxDynamicSharedMemorySize, SM_TOTAL);

    int sm_count = 148;
    cudaDeviceGetAttribute(&sm_count, cudaDevAttrMultiProcessorCount, 0);

    gated_spiral_kernel<<<3*sm_count, NTHREADS, SM_TOTAL>>>(
        x, indices, weight, gate_b, out);
}

// round 14
// speedup vs baseline: 1.1799x; 1.1799x over previous
#include <cuda_runtime.h>
#include <cuda_bf16.h>
#include <cuda_fp16.h>
#include <cstdint>

#define N_NODES  50000
#define SEQ      12
#define CH       128
#define BS       4
#define TM       64           // nodes per tile
#define NTHREADS 256
#define AP       136          // bf16 A-tile pitch (elements)
#define GP       132          // gate fp32 pitch
#define NCONV    148          // converter blocks (1/SM)
#define ELEMS_PB (N_NODES*(CH/4))          // 1.6M uint2 per batch
#define CHUNK    ((ELEMS_PB + NCONV - 1)/NCONV)

typedef unsigned long long ull;
typedef unsigned int       uint32;

// ---- smem: A tile, overlaid by gate after MMA ----
#define SM_A0    0                      // A hi bf16 [64][AP]   17408 B
#define SM_A1    17408                  // A lo                 17408 B
#define SM_GATE  0                      // fp32 [64][GP] 33792 B, overlays A0+A1
#define SM_TOTAL 34816

// W fragments, coalesced: uint4 (h0,h1,l0,l1) at [((ns*8+kb)*4+nb)*32 + lane]
__device__ uint4 g_wfrag[4*8*4*32];     // 64 KB

// fp16 shadow of x: 4 halves per uint2 (51.2 MB, L2-resident)
__device__ uint2 g_xh[BS*N_NODES*(CH/4)];

// per-batch conversion-complete counters (reset by setup_kernel each launch)
__device__ int g_flag[BS];

__device__ __forceinline__ ull fma2(ull a, ull b, ull c){ull d;asm("fma.rn.f32x2 %0,%1,%2,%3;":"=l"(d):"l"(a),"l"(b),"l"(c));return d;}
__device__ __forceinline__ ull mul2(ull a, ull b){ull d;asm("mul.rn.f32x2 %0,%1,%2;":"=l"(d):"l"(a),"l"(b));return d;}
__device__ __forceinline__ ull add2(ull a, ull b){ull d;asm("add.rn.f32x2 %0,%1,%2;":"=l"(d):"l"(a),"l"(b));return d;}
__device__ __forceinline__ ull dup2(float a){ull d;asm("mov.b64 %0,{%1,%1};":"=l"(d):"f"(a));return d;}
__device__ __forceinline__ ull pack2(float lo,float hi){ull d;asm("mov.b64 %0,{%1,%2};":"=l"(d):"f"(lo),"f"(hi));return d;}

__device__ __forceinline__ uint32 smem_u32(const void* p){
    uint32 a; asm("{.reg .u64 t; cvta.to.shared.u64 t,%1; cvt.u32.u64 %0,t;}":"=r"(a):"l"(p)); return a;
}
__device__ __forceinline__ int ld_acq(const int* p){
    int v; asm volatile("ld.acquire.gpu.global.b32 %0,[%1];":"=r"(v):"l"(p)); return v;
}
__device__ __forceinline__ void split2(float x, float y, uint32& hi, uint32& lo){
    __nv_bfloat16 bx = __float2bfloat16_rn(x), by = __float2bfloat16_rn(y);
    float rx = x - __bfloat162float(bx), ry = y - __bfloat162float(by);
    __nv_bfloat162 h; h.x = bx; h.y = by;
    __nv_bfloat162 l; l.x = __float2bfloat16_rn(rx); l.y = __float2bfloat16_rn(ry);
    hi = *reinterpret_cast<uint32*>(&h);
    lo = *reinterpret_cast<uint32*>(&l);
}
__device__ __forceinline__ void ldsm_x4(uint32& a0,uint32& a1,uint32& a2,uint32& a3, uint32 addr){
    asm volatile("ldmatrix.sync.aligned.m8n8.x4.shared.b16 {%0,%1,%2,%3},[%4];"
                 : "=r"(a0),"=r"(a1),"=r"(a2),"=r"(a3) : "r"(addr));
}
__device__ __forceinline__ void hmma2(float* c, const uint32* a, uint32 b0, uint32 b1){
    asm volatile("mma.sync.aligned.m16n8k16.row.col.f32.bf16.bf16.f32 "
                 "{%0,%1,%2,%3},{%4,%5,%6,%7},{%8,%9},{%0,%1,%2,%3};"
                 : "+f"(c[0]),"+f"(c[1]),"+f"(c[2]),"+f"(c[3])
                 : "r"(a[0]),"r"(a[1]),"r"(a[2]),"r"(a[3]),"r"(b0),"r"(b1));
}
__device__ __forceinline__ void ldg_cg_v4(const float* p, ull& x, ull& y){
    asm("ld.global.cg.v2.u64 {%0,%1},[%2];" : "=l"(x),"=l"(y) : "l"(p));
}
__device__ __forceinline__ void ldg_cg_v2u32(const uint2* p, uint32& a, uint32& b){
    asm("ld.global.cg.v2.u32 {%0,%1},[%2];" : "=r"(a),"=r"(b) : "l"(p));
}
__device__ __forceinline__ float4 ldg_cs_f4(const float4* p){
    float4 v;
    asm("ld.global.cs.v4.f32 {%0,%1,%2,%3},[%4];"
        : "=f"(v.x),"=f"(v.y),"=f"(v.z),"=f"(v.w) : "l"(p));
    return v;
}
__device__ __forceinline__ uint2 cvt_h4(float4 v){
    __half2 h0 = __floats2half2_rn(v.x, v.y);
    __half2 h1 = __floats2half2_rn(v.z, v.w);
    uint2 o;
    o.x = *reinterpret_cast<uint32*>(&h0);
    o.y = *reinterpret_cast<uint32*>(&h1);
    return o;
}

// ---- setup kernel: reset flags + build HMMA B fragments ----
__global__ void setup_kernel(const float* __restrict__ gate_w)
{
    int slot = blockIdx.x*blockDim.x + threadIdx.x;   // 0..1023
    if (slot < BS) g_flag[slot] = 0;
    if (slot >= 4*8*32) return;
    int lane = slot & 31;
    int kb   = (slot >> 5) & 7;
    int ns   = slot >> 8;
    #pragma unroll
    for (int nb = 0; nb < 4; nb++) {
        int n = ns*32 + nb*8 + (lane >> 2);
        uint32 h[2], l[2];
        #pragma unroll
        for (int i = 0; i < 2; i++) {
            int k0 = kb*16 + i*8 + (lane & 3)*2;
            split2(gate_w[n*CH + k0], gate_w[n*CH + k0 + 1], h[i], l[i]);
        }
        uint4 v; v.x = h[0]; v.y = h[1]; v.z = l[0]; v.w = l[1];
        g_wfrag[(((ns << 3) + kb)*4 + nb)*32 + lane] = v;
    }
}

__global__ void __launch_bounds__(NTHREADS, 3)
gated_spiral_kernel(const float* __restrict__ x,
                    const int*   __restrict__ indices,
                    const float* __restrict__ weight,
                    const float* __restrict__ gate_b,
                    float*       __restrict__ out)
{
    extern __shared__ char smem[];
    const uint32 sb = smem_u32(smem);
    float* gate_s = (float*)(smem + SM_GATE);

    const int tid  = threadIdx.x;
    const int wid  = tid >> 5;
    const int lane = tid & 31;

    // =================== converter role (blocks 0..NCONV-1) ===================
    // Batch-major, explicit 4-deep pipeline for guaranteed MLP.
    if (blockIdx.x < NCONV) {
        const float4* xv = reinterpret_cast<const float4*>(x);
        #pragma unroll 1
        for (int b = 0; b < BS; b++) {
            const int base  = b*ELEMS_PB;
            const int begin = base + blockIdx.x*CHUNK;
            const int end   = min(begin + CHUNK, base + ELEMS_PB);
            int i = begin + tid;
            for (; i + 3*NTHREADS < end; i += 4*NTHREADS) {
                float4 v0 = ldg_cs_f4(xv + i);
                float4 v1 = ldg_cs_f4(xv + i + NTHREADS);
                float4 v2 = ldg_cs_f4(xv + i + 2*NTHREADS);
                float4 v3 = ldg_cs_f4(xv + i + 3*NTHREADS);
                g_xh[i]              = cvt_h4(v0);
                g_xh[i +   NTHREADS] = cvt_h4(v1);
                g_xh[i + 2*NTHREADS] = cvt_h4(v2);
                g_xh[i + 3*NTHREADS] = cvt_h4(v3);
            }
            for (; i < end; i += NTHREADS)
                g_xh[i] = cvt_h4(ldg_cs_f4(xv + i));
            __threadfence();
            __syncthreads();
            if (tid == 0) atomicAdd(&g_flag[b], 1);
        }
        return;   // converters exit; compute isn't block-limited
    }

    // =================== compute role ===================
    const int cidx   = blockIdx.x - NCONV;
    const int stride = gridDim.x - NCONV;

    const ull bias0 = *reinterpret_cast<const ull*>(gate_b + lane*4);
    const ull bias1 = *reinterpret_cast<const ull*>(gate_b + lane*4 + 2);

    // MMA role: 8 warps = 2m x 4n grid; warp tile m32 x n32
    const int ms = wid & 1;
    const int ns = wid >> 1;
    const uint32 aoff0 = (uint32)((ms*32      + (lane & 15))*AP + (lane >> 4)*8) * 2;
    const uint32 aoff1 = (uint32)((ms*32 + 16 + (lane & 15))*AP + (lane >> 4)*8) * 2;

    const int tiles_per_batch = (N_NODES + TM - 1) / TM;   // 782
    const int total_tiles     = BS * tiles_per_batch;      // 3128

    // ---- stage A tile (fp32 source: GEMM accuracy unchanged; no flag dependency) ----
    auto stage = [&](int tt) {
        const int bb  = tt / tiles_per_batch;
        const int vv0 = (tt - bb * tiles_per_batch) * TM;
        const int nv  = min(TM, N_NODES - vv0);
        const float* xs = x + (size_t)bb * (size_t)N_NODES * CH;
        #pragma unroll
        for (int k = 0; k < 8; k++) {                  // 64*32 float4 / 256 thr
            int i  = tid + k*NTHREADS;
            int r  = i >> 5;
            int k4 = (i & 31) << 2;
            const float* p = xs + (size_t)(vv0 + min(r, nv - 1))*CH + k4;
            ull lo, hi2; ldg_cg_v4(p, lo, hi2);
            float2 v01 = *reinterpret_cast<float2*>(&lo);
            float2 v23 = *reinterpret_cast<float2*>(&hi2);
            uint32 h0,l0,h1,l1;
            split2(v01.x, v01.y, h0, l0);
            split2(v23.x, v23.y, h1, l1);
            uint32 o = (uint32)(r*AP + k4) * 2;
            *(ull*)(smem + SM_A0 + o) = ((ull)h1 << 32) | h0;
            *(ull*)(smem + SM_A1 + o) = ((ull)l1 << 32) | l0;
        }
    };

    int t = cidx;
    if (t < total_tiles) stage(t);

    for (; t < total_tiles; t += stride) {
        const int b      = t / tiles_per_batch;
        const int v0     = (t - b * tiles_per_batch) * TM;
        const int nvalid = min(TM, N_NODES - v0);
        const uint2* __restrict__ xhb = g_xh + (size_t)b * (size_t)N_NODES * (CH/4);

        __syncthreads();   // A(t) visible

        // ---- HMMA: gate = A x W^T; one nb-fragment live at a time ----
        float acc[2][4][4];
        #pragma unroll
        for (int mi = 0; mi < 2; mi++)
            #pragma unroll
            for (int nb = 0; nb < 4; nb++)
                #pragma unroll
                for (int j = 0; j < 4; j++) acc[mi][nb][j] = 0.f;

        #pragma unroll
        for (int kb = 0; kb < 8; kb++) {
            const uint32 ko = kb*32;
            uint32 ah[2][4], al[2][4];
            ldsm_x4(ah[0][0],ah[0][1],ah[0][2],ah[0][3], sb + SM_A0 + aoff0 + ko);
            ldsm_x4(ah[1][0],ah[1][1],ah[1][2],ah[1][3], sb + SM_A0 + aoff1 + ko);
            ldsm_x4(al[0][0],al[0][1],al[0][2],al[0][3], sb + SM_A1 + aoff0 + ko);
            ldsm_x4(al[1][0],al[1][1],al[1][2],al[1][3], sb + SM_A1 + aoff1 + ko);
            const uint4* wp = g_wfrag + (((ns << 3) + kb) << 2)*32 + lane;
            #pragma unroll
            for (int nb = 0; nb < 4; nb++) {
                uint4 w = wp[nb*32];                    // (h0,h1,l0,l1)
                #pragma unroll
                for (int mi = 0; mi < 2; mi++) {
                    hmma2(acc[mi][nb], ah[mi], w.x, w.y);   // hi*hi
                    hmma2(acc[mi][nb], ah[mi], w.z, w.w);   // hi*lo
                    hmma2(acc[mi][nb], al[mi], w.x, w.y);   // lo*hi
                }
            }
        }
        __syncthreads();   // all ldsm retired before gate overlays A

        // ---- Epilogue: acc -> gate_s ----
        #pragma unroll
        for (int mi = 0; mi < 2; mi++) {
            int r0 = ms*32 + mi*16 + (lane >> 2);
            #pragma unroll
            for (int nb = 0; nb < 4; nb++) {
                int c = ns*32 + nb*8 + (lane & 3)*2;
                *reinterpret_cast<ull*>(gate_s + r0*GP + c)     = pack2(acc[mi][nb][0], acc[mi][nb][1]);
                *reinterpret_cast<ull*>(gate_s + (r0+8)*GP + c) = pack2(acc[mi][nb][2], acc[mi][nb][3]);
            }
        }

        // ---- wait for this batch's fp16 shadow (nanosleep backoff, no L2 hammer) ----
        if (tid == 0) {
            while (ld_acq(&g_flag[b]) < NCONV) __nanosleep(100);
        }
        __syncthreads();   // gate visible + xh(b) ready

        // ---- Gather (fp16 source): warp-per-row; lane = 4 channels (8B LDG) ----
        #pragma unroll 1
        for (int nn = 0; nn < 8; nn++) {
            const int node = wid*8 + nn;
            if (node >= nvalid) break;
            const int base = (v0 + node)*SEQ;
            int4   ia = *reinterpret_cast<const int4*>(indices + base);
            int4   ib = *reinterpret_cast<const int4*>(indices + base + 4);
            int4   ic = *reinterpret_cast<const int4*>(indices + base + 8);
            float4 wa = *reinterpret_cast<const float4*>(weight + base);
            float4 wb = *reinterpret_cast<const float4*>(weight + base + 4);
            float4 wc = *reinterpret_cast<const float4*>(weight + base + 8);
            ull a0 = 0, a1 = 0;
            #define GACC(II, WW) { \
                const uint2* src = xhb + (size_t)(uint32)(II)*(CH/4) + lane; \
                uint32 u0, u1; ldg_cg_v2u32(src, u0, u1); \
                float2 f0 = __half22float2(*reinterpret_cast<__half2*>(&u0)); \
                float2 f1 = __half22float2(*reinterpret_cast<__half2*>(&u1)); \
                ull W = dup2(WW); \
                a0 = fma2(W, pack2(f0.x, f0.y), a0); \
                a1 = fma2(W, pack2(f1.x, f1.y), a1); }
            GACC(ia.x, wa.x) GACC(ia.y, wa.y) GACC(ia.z, wa.z) GACC(ia.w, wa.w)
            GACC(ib.x, wb.x) GACC(ib.y, wb.y) GACC(ib.z, wb.z) GACC(ib.w, wb.w)
            GACC(ic.x, wc.x) GACC(ic.y, wc.y) GACC(ic.z, wc.z) GACC(ic.w, wc.w)
            #undef GACC
            ulonglong2 gp = *reinterpret_cast<const ulonglong2*>(gate_s + node*GP + lane*4);
            ull o0 = mul2(a0, add2(gp.x, bias0));
            ull o1 = mul2(a1, add2(gp.y, bias1));
            float* op = out + ((size_t)b*N_NODES + (size_t)(v0 + node))*CH + lane*4;
            asm volatile("st.global.cs.v2.b64 [%0], {%1,%2};" :: "l"(op), "l"(o0), "l"(o1) : "memory");
        }

        __syncthreads();   // gather done reading gate

        // ---- Stage next tile (overwrites A/gate smem) ----
        const int nxt = t + stride;
        if (nxt < total_tiles) stage(nxt);
    }
}

extern "C" void kernel_launch(void* const* d_in, const int* in_sizes, int n_in,
                              void* d_out, int out_size)
{
    (void)in_sizes; (void)n_in; (void)out_size;
    const float* x       = (const float*)d_in[0];
    const int*   indices = (const int*)  d_in[1];
    const float* weight  = (const float*)d_in[2];
    const float* gate_w  = (const float*)d_in[3];
    const float* gate_b  = (const float*)d_in[4];
    float*       out     = (float*)d_out;

    setup_kernel<<<4, 256>>>(gate_w);

    cudaFuncSetAttribute(gated_spiral_kernel,
                         cudaFuncAttributeMaxDynamicSharedMemorySize, SM_TOTAL);

    int sm_count = 148;
    cudaDeviceGetAttribute(&sm_count, cudaDevAttrMultiProcessorCount, 0);

    gated_spiral_kernel<<<3*sm_count, NTHREADS, SM_TOTAL>>>(
        x, indices, weight, gate_b, out);
}

// round 16
// speedup vs baseline: 1.4679x; 1.2441x over previous
#include <cuda_runtime.h>
#include <cuda_bf16.h>
#include <cuda_fp16.h>
#include <cstdint>

#define N_NODES  50000
#define SEQ      12
#define CH       128
#define BS       4
#define TM       64           // nodes per tile
#define NTHREADS 256
#define AP       136          // bf16 A-tile pitch (elements)
#define GP       132          // gate fp32 pitch

typedef unsigned long long ull;
typedef unsigned int       uint32;

// ---- smem: A tile, overlaid by gate after MMA ----
#define SM_A0    0                      // A hi bf16 [64][AP]   17408 B
#define SM_A1    17408                  // A lo                 17408 B
#define SM_GATE  0                      // fp32 [64][GP] 33792 B, overlays A0+A1
#define SM_TOTAL 34816

// W fragments, coalesced: uint4 (h0,h1,l0,l1) at [((ns*8+kb)*4+nb)*32 + lane]
__device__ uint4 g_wfrag[4*8*4*32];     // 64 KB

// fp16 shadow of x: 4 halves per uint2 (51.2 MB, L2-resident). Written by
// convert kernel BEFORE main launches (same stream, serial).
__device__ uint2 g_xh[BS*N_NODES*(CH/4)];

__device__ __forceinline__ ull fma2(ull a, ull b, ull c){ull d;asm("fma.rn.f32x2 %0,%1,%2,%3;":"=l"(d):"l"(a),"l"(b),"l"(c));return d;}
__device__ __forceinline__ ull mul2(ull a, ull b){ull d;asm("mul.rn.f32x2 %0,%1,%2;":"=l"(d):"l"(a),"l"(b));return d;}
__device__ __forceinline__ ull add2(ull a, ull b){ull d;asm("add.rn.f32x2 %0,%1,%2;":"=l"(d):"l"(a),"l"(b));return d;}
__device__ __forceinline__ ull dup2(float a){ull d;asm("mov.b64 %0,{%1,%1};":"=l"(d):"f"(a));return d;}
__device__ __forceinline__ ull pack2(float lo,float hi){ull d;asm("mov.b64 %0,{%1,%2};":"=l"(d):"f"(lo),"f"(hi));return d;}

__device__ __forceinline__ uint32 smem_u32(const void* p){
    uint32 a; asm("{.reg .u64 t; cvta.to.shared.u64 t,%1; cvt.u32.u64 %0,t;}":"=r"(a):"l"(p)); return a;
}
__device__ __forceinline__ void split2(float x, float y, uint32& hi, uint32& lo){
    __nv_bfloat16 bx = __float2bfloat16_rn(x), by = __float2bfloat16_rn(y);
    float rx = x - __bfloat162float(bx), ry = y - __bfloat162float(by);
    __nv_bfloat162 h; h.x = bx; h.y = by;
    __nv_bfloat162 l; l.x = __float2bfloat16_rn(rx); l.y = __float2bfloat16_rn(ry);
    hi = *reinterpret_cast<uint32*>(&h);
    lo = *reinterpret_cast<uint32*>(&l);
}
__device__ __forceinline__ void ldsm_x4(uint32& a0,uint32& a1,uint32& a2,uint32& a3, uint32 addr){
    asm volatile("ldmatrix.sync.aligned.m8n8.x4.shared.b16 {%0,%1,%2,%3},[%4];"
                 : "=r"(a0),"=r"(a1),"=r"(a2),"=r"(a3) : "r"(addr));
}
__device__ __forceinline__ void hmma2(float* c, const uint32* a, uint32 b0, uint32 b1){
    asm volatile("mma.sync.aligned.m16n8k16.row.col.f32.bf16.bf16.f32 "
                 "{%0,%1,%2,%3},{%4,%5,%6,%7},{%8,%9},{%0,%1,%2,%3};"
                 : "+f"(c[0]),"+f"(c[1]),"+f"(c[2]),"+f"(c[3])
                 : "r"(a[0]),"r"(a[1]),"r"(a[2]),"r"(a[3]),"r"(b0),"r"(b1));
}
__device__ __forceinline__ void ldg_cg_v2u32(const uint2* p, uint32& a, uint32& b){
    asm("ld.global.cg.v2.u32 {%0,%1},[%2];" : "=r"(a),"=r"(b) : "l"(p));
}

// ---- pre-kernel: x fp32 -> fp16 shadow (proven 22us, DRAM-bound) ----
__global__ void convert_x_kernel(const float* __restrict__ x)
{
    const int total = BS*N_NODES*(CH/4);   // 6.4M uint2
    for (int i = blockIdx.x*blockDim.x + threadIdx.x; i < total; i += gridDim.x*blockDim.x) {
        float4 v;
        asm("ld.global.cs.v4.f32 {%0,%1,%2,%3},[%4];"
            : "=f"(v.x),"=f"(v.y),"=f"(v.z),"=f"(v.w)
            : "l"(reinterpret_cast<const float4*>(x) + i));
        __half2 h0 = __floats2half2_rn(v.x, v.y);
        __half2 h1 = __floats2half2_rn(v.z, v.w);
        uint2 o;
        o.x = *reinterpret_cast<uint32*>(&h0);
        o.y = *reinterpret_cast<uint32*>(&h1);
        g_xh[i] = o;
    }
}

// ---- build kernel: HMMA B fragments, coalesced (h0,h1,l0,l1) ----
__global__ void build_wfrag_kernel(const float* __restrict__ gate_w)
{
    int slot = blockIdx.x*blockDim.x + threadIdx.x;   // 0..1023
    if (slot >= 4*8*32) return;
    int lane = slot & 31;
    int kb   = (slot >> 5) & 7;
    int ns   = slot >> 8;
    #pragma unroll
    for (int nb = 0; nb < 4; nb++) {
        int n = ns*32 + nb*8 + (lane >> 2);
        uint32 h[2], l[2];
        #pragma unroll
        for (int i = 0; i < 2; i++) {
            int k0 = kb*16 + i*8 + (lane & 3)*2;
            split2(gate_w[n*CH + k0], gate_w[n*CH + k0 + 1], h[i], l[i]);
        }
        uint4 v; v.x = h[0]; v.y = h[1]; v.z = l[0]; v.w = l[1];
        g_wfrag[(((ns << 3) + kb)*4 + nb)*32 + lane] = v;
    }
}

__global__ void __launch_bounds__(NTHREADS, 3)
gated_spiral_kernel(const int*   __restrict__ indices,
                    const float* __restrict__ weight,
                    const float* __restrict__ gate_b,
                    float*       __restrict__ out)
{
    extern __shared__ char smem[];
    const uint32 sb = smem_u32(smem);
    float* gate_s = (float*)(smem + SM_GATE);

    const int tid  = threadIdx.x;
    const int wid  = tid >> 5;
    const int lane = tid & 31;

    const ull bias0 = *reinterpret_cast<const ull*>(gate_b + lane*4);
    const ull bias1 = *reinterpret_cast<const ull*>(gate_b + lane*4 + 2);

    // MMA role: 8 warps = 2m x 4n grid; warp tile m32 x n32
    const int ms = wid & 1;
    const int ns = wid >> 1;
    const uint32 aoff0 = (uint32)((ms*32      + (lane & 15))*AP + (lane >> 4)*8) * 2;
    const uint32 aoff1 = (uint32)((ms*32 + 16 + (lane & 15))*AP + (lane >> 4)*8) * 2;

    const int tiles_per_batch = (N_NODES + TM - 1) / TM;   // 782
    const int total_tiles     = BS * tiles_per_batch;      // 3128

    // ---- stage A tile FROM THE FP16 SHADOW (8B loads; exact bf16x2 split) ----
    auto stage = [&](int tt) {
        const int bb  = tt / tiles_per_batch;
        const int vv0 = (tt - bb * tiles_per_batch) * TM;
        const int nv  = min(TM, N_NODES - vv0);
        const uint2* xs = g_xh + (size_t)bb * (size_t)N_NODES * (CH/4);
        #pragma unroll
        for (int k = 0; k < 8; k++) {                  // 64 rows x 32 segs / 256 thr
            int i  = tid + k*NTHREADS;
            int r  = i >> 5;
            int sg = i & 31;                            // 4-channel segment
            const uint2* p = xs + (size_t)(vv0 + min(r, nv - 1))*(CH/4) + sg;
            uint32 u0, u1; ldg_cg_v2u32(p, u0, u1);
            float2 f01 = __half22float2(*reinterpret_cast<__half2*>(&u0));
            float2 f23 = __half22float2(*reinterpret_cast<__half2*>(&u1));
            uint32 h0,l0,h1,l1;
            split2(f01.x, f01.y, h0, l0);
            split2(f23.x, f23.y, h1, l1);
            uint32 o = (uint32)(r*AP + (sg << 2)) * 2;
            *(ull*)(smem + SM_A0 + o) = ((ull)h1 << 32) | h0;
            *(ull*)(smem + SM_A1 + o) = ((ull)l1 << 32) | l0;
        }
    };

    int t = blockIdx.x;
    if (t < total_tiles) stage(t);

    for (; t < total_tiles; t += gridDim.x) {
        const int b      = t / tiles_per_batch;
        const int v0     = (t - b * tiles_per_batch) * TM;
        const int nvalid = min(TM, N_NODES - v0);
        const uint2* __restrict__ xhb = g_xh + (size_t)b * (size_t)N_NODES * (CH/4);

        __syncthreads();   // A(t) visible

        // ---- HMMA: gate = A x W^T; one nb-fragment live at a time ----
        float acc[2][4][4];
        #pragma unroll
        for (int mi = 0; mi < 2; mi++)
            #pragma unroll
            for (int nb = 0; nb < 4; nb++)
                #pragma unroll
                for (int j = 0; j < 4; j++) acc[mi][nb][j] = 0.f;

        #pragma unroll
        for (int kb = 0; kb < 8; kb++) {
            const uint32 ko = kb*32;
            uint32 ah[2][4], al[2][4];
            ldsm_x4(ah[0][0],ah[0][1],ah[0][2],ah[0][3], sb + SM_A0 + aoff0 + ko);
            ldsm_x4(ah[1][0],ah[1][1],ah[1][2],ah[1][3], sb + SM_A0 + aoff1 + ko);
            ldsm_x4(al[0][0],al[0][1],al[0][2],al[0][3], sb + SM_A1 + aoff0 + ko);
            ldsm_x4(al[1][0],al[1][1],al[1][2],al[1][3], sb + SM_A1 + aoff1 + ko);
            const uint4* wp = g_wfrag + (((ns << 3) + kb) << 2)*32 + lane;
            #pragma unroll
            for (int nb = 0; nb < 4; nb++) {
                uint4 w = wp[nb*32];                    // (h0,h1,l0,l1)
                #pragma unroll
                for (int mi = 0; mi < 2; mi++) {
                    hmma2(acc[mi][nb], ah[mi], w.x, w.y);   // hi*hi
                    hmma2(acc[mi][nb], ah[mi], w.z, w.w);   // hi*lo
                    hmma2(acc[mi][nb], al[mi], w.x, w.y);   // lo*hi
                }
            }
        }
        __syncthreads();   // all ldsm retired before gate overlays A

        // ---- Epilogue: acc -> gate_s ----
        #pragma unroll
        for (int mi = 0; mi < 2; mi++) {
            int r0 = ms*32 + mi*16 + (lane >> 2);
            #pragma unroll
            for (int nb = 0; nb < 4; nb++) {
                int c = ns*32 + nb*8 + (lane & 3)*2;
                *reinterpret_cast<ull*>(gate_s + r0*GP + c)     = pack2(acc[mi][nb][0], acc[mi][nb][1]);
                *reinterpret_cast<ull*>(gate_s + (r0+8)*GP + c) = pack2(acc[mi][nb][2], acc[mi][nb][3]);
            }
        }
        __syncthreads();   // gate visible

        // ---- Gather (fp16 source): warp-per-row; lane = 4 channels (8B LDG) ----
        #pragma unroll 1
        for (int nn = 0; nn < 8; nn++) {
            const int node = wid*8 + nn;
            if (node >= nvalid) break;
            const int base = (v0 + node)*SEQ;
            int4   ia = *reinterpret_cast<const int4*>(indices + base);
            int4   ib = *reinterpret_cast<const int4*>(indices + base + 4);
            int4   ic = *reinterpret_cast<const int4*>(indices + base + 8);
            float4 wa = *reinterpret_cast<const float4*>(weight + base);
            float4 wb = *reinterpret_cast<const float4*>(weight + base + 4);
            float4 wc = *reinterpret_cast<const float4*>(weight + base + 8);
            ull a0 = 0, a1 = 0;
            #define GACC(II, WW) { \
                const uint2* src = xhb + (size_t)(uint32)(II)*(CH/4) + lane; \
                uint32 u0, u1; ldg_cg_v2u32(src, u0, u1); \
                float2 f0 = __half22float2(*reinterpret_cast<__half2*>(&u0)); \
                float2 f1 = __half22float2(*reinterpret_cast<__half2*>(&u1)); \
                ull W = dup2(WW); \
                a0 = fma2(W, pack2(f0.x, f0.y), a0); \
                a1 = fma2(W, pack2(f1.x, f1.y), a1); }
            GACC(ia.x, wa.x) GACC(ia.y, wa.y) GACC(ia.z, wa.z) GACC(ia.w, wa.w)
            GACC(ib.x, wb.x) GACC(ib.y, wb.y) GACC(ib.z, wb.z) GACC(ib.w, wb.w)
            GACC(ic.x, wc.x) GACC(ic.y, wc.y) GACC(ic.z, wc.z) GACC(ic.w, wc.w)
            #undef GACC
            ulonglong2 gp = *reinterpret_cast<const ulonglong2*>(gate_s + node*GP + lane*4);
            ull o0 = mul2(a0, add2(gp.x, bias0));
            ull o1 = mul2(a1, add2(gp.y, bias1));
            float* op = out + ((size_t)b*N_NODES + (size_t)(v0 + node))*CH + lane*4;
            float2 q0 = *reinterpret_cast<float2*>(&o0);
            float2 q1 = *reinterpret_cast<float2*>(&o1);
            asm volatile("st.global.cs.v4.f32 [%0], {%1,%2,%3,%4};"
                         :: "l"(op), "f"(q0.x), "f"(q0.y), "f"(q1.x), "f"(q1.y) : "memory");
        }

        __syncthreads();   // gather done reading gate

        // ---- Stage next tile (overwrites A/gate smem) ----
        const int nxt = t + gridDim.x;
        if (nxt < total_tiles) stage(nxt);
    }
}

extern "C" void kernel_launch(void* const* d_in, const int* in_sizes, int n_in,
                              void* d_out, int out_size)
{
    (void)in_sizes; (void)n_in; (void)out_size;
    const float* x       = (const float*)d_in[0];
    const int*   indices = (const int*)  d_in[1];
    const float* weight  = (const float*)d_in[2];
    const float* gate_w  = (const float*)d_in[3];
    const float* gate_b  = (const float*)d_in[4];
    float*       out     = (float*)d_out;

    convert_x_kernel<<<2048, 256>>>(x);
    build_wfrag_kernel<<<4, 256>>>(gate_w);

    cudaFuncSetAttribute(gated_spiral_kernel,
                         cudaFuncAttributeMaxDynamicSharedMemorySize, SM_TOTAL);

    int sm_count = 148;
    cudaDeviceGetAttribute(&sm_count, cudaDevAttrMultiProcessorCount, 0);

    gated_spiral_kernel<<<3*sm_count, NTHREADS, SM_TOTAL>>>(
        indices, weight, gate_b, out);
}